// round 16
// baseline (speedup 1.0000x reference)
#include <cuda_runtime.h>
#include <cstdint>
#include <math.h>

#define BDIM 512
#define NCHUNK 25
#define ALD 36            // A/B smem row stride (floats)
#define BLD 36            // band cell stride (floats): 32 ch + 4 pad
#define EPSF 1e-7f

// smem float offsets
#define OFF_BIAS 0        // 64
#define OFF_CELL 64       // 512
#define OFF_COEF 576      // 128*8 = 1024
#define OFF_AHI0 1600     // 128*36 = 4608 each
#define OFF_ALO0 6208
#define OFF_AHI1 10816
#define OFF_ALO1 15424
#define OFF_BHI0 20032    // 64*36 = 2304 each
#define OFF_BLO0 22336
#define OFF_BHI1 24640
#define OFF_BLO1 26944
#define OFF_BAND 29248    // 512*36 = 18432
#define SMEM_FLOATS 47680 // 190720 bytes -> 1 CTA/SM

__device__ __forceinline__ uint32_t to_tf32(float f) {
    uint32_t r;
    asm("cvt.rna.tf32.f32 %0, %1;" : "=r"(r) : "f"(f));
    return r;
}

__device__ __forceinline__ void mma8(float* d,
        uint32_t a0, uint32_t a1, uint32_t a2, uint32_t a3,
        uint32_t b0, uint32_t b1) {
    asm volatile(
        "mma.sync.aligned.m16n8k8.row.col.f32.tf32.tf32.f32 "
        "{%0,%1,%2,%3}, {%4,%5,%6,%7}, {%8,%9}, {%0,%1,%2,%3};"
        : "+f"(d[0]), "+f"(d[1]), "+f"(d[2]), "+f"(d[3])
        : "r"(a0), "r"(a1), "r"(a2), "r"(a3), "r"(b0), "r"(b1));
}

// materialize chunk ch (one rotation position) into Ahi/Alo.
// task t = (px, c4), c4 fastest within warp -> conflict-light gather.
__device__ __forceinline__ void materialize(
    float* __restrict__ Ahi, float* __restrict__ Alo,
    const float* __restrict__ band, const float* __restrict__ tb,
    int ch, int tid)
{
    int py = ch / 5;
    float xg = (float)(ch - py * 5 + 1);
    float yg = (float)(py + 1);
    #pragma unroll
    for (int it = 0; it < 2; it++) {
        int t = tid + it * BDIM;
        int px = t >> 3, c4 = t & 7;
        int orow = px >> 6, ocol = px & 63;
        float4 w = make_float4(0.f, 0.f, 0.f, 0.f);
        unsigned cc00 = 0, cc01 = 0, cc10 = 0, cc11 = 0;
        if (ocol < 58) {
            float A0 = tb[px * 8 + 0], A1 = tb[px * 8 + 1], A2 = tb[px * 8 + 2];
            float A3 = tb[px * 8 + 3], A5 = tb[px * 8 + 4];
            float x_in = A0 * xg + A1 * yg + A2;
            float y_in = A3 * xg + A0 * yg + A5;
            float x0f = floorf(x_in), y0f = floorf(y_in);
            float wx1 = x_in - x0f, wx0 = 1.f - wx1;
            float wy1 = y_in - y0f, wy0 = 1.f - wy1;
            int ix0 = (int)x0f, iy0 = (int)y0f;
            int ix1 = ix0 + 1, iy1 = iy0 + 1;
            float vx0 = (ix0 >= 0 && ix0 < 7) ? 1.f : 0.f;
            float vx1 = (ix1 >= 0 && ix1 < 7) ? 1.f : 0.f;
            float vy0 = (iy0 >= 0 && iy0 < 7) ? 1.f : 0.f;
            float vy1 = (iy1 >= 0 && iy1 < 7) ? 1.f : 0.f;
            int cx0 = min(max(ix0, 0), 6), cx1 = min(max(ix1, 0), 6);
            int cy0 = min(max(iy0, 0), 6), cy1 = min(max(iy1, 0), 6);
            w = make_float4(wy0 * wx0 * vy0 * vx0, wy0 * wx1 * vy0 * vx1,
                            wy1 * wx0 * vy1 * vx0, wy1 * wx1 * vy1 * vx1);
            cc00 = (orow + cy0) * 64 + ocol + cx0;
            cc01 = (orow + cy0) * 64 + ocol + cx1;
            cc10 = (orow + cy1) * 64 + ocol + cx0;
            cc11 = (orow + cy1) * 64 + ocol + cx1;
        }
        int base = c4 * 4;
        const float4 v0 = *reinterpret_cast<const float4*>(band + cc00 * BLD + base);
        const float4 v1 = *reinterpret_cast<const float4*>(band + cc01 * BLD + base);
        const float4 v2 = *reinterpret_cast<const float4*>(band + cc10 * BLD + base);
        const float4 v3 = *reinterpret_cast<const float4*>(band + cc11 * BLD + base);
        float rx = fmaf(w.x, v0.x, fmaf(w.y, v1.x, fmaf(w.z, v2.x, w.w * v3.x)));
        float ry = fmaf(w.x, v0.y, fmaf(w.y, v1.y, fmaf(w.z, v2.y, w.w * v3.y)));
        float rz = fmaf(w.x, v0.z, fmaf(w.y, v1.z, fmaf(w.z, v2.z, w.w * v3.z)));
        float rw = fmaf(w.x, v0.w, fmaf(w.y, v1.w, fmaf(w.z, v2.w, w.w * v3.w)));
        uint32_t hx = to_tf32(rx), hy = to_tf32(ry), hz = to_tf32(rz), hw = to_tf32(rw);
        uint32_t lx = to_tf32(rx - __uint_as_float(hx));
        uint32_t ly = to_tf32(ry - __uint_as_float(hy));
        uint32_t lz = to_tf32(rz - __uint_as_float(hz));
        uint32_t lw = to_tf32(rw - __uint_as_float(hw));
        *reinterpret_cast<uint4*>(Ahi + px * ALD + base) = make_uint4(hx, hy, hz, hw);
        *reinterpret_cast<uint4*>(Alo + px * ALD + base) = make_uint4(lx, ly, lz, lw);
    }
}

__device__ __forceinline__ void stageB(
    float* __restrict__ Bhi, float* __restrict__ Blo,
    const float* __restrict__ Wg, int ch, int tid)
{
    int f = tid >> 3, kq = tid & 7;
    float4 v = *reinterpret_cast<const float4*>(Wg + f * 800 + ch * 32 + kq * 4);
    uint32_t hx = to_tf32(v.x), hy = to_tf32(v.y), hz = to_tf32(v.z), hw = to_tf32(v.w);
    uint32_t lx = to_tf32(v.x - __uint_as_float(hx));
    uint32_t ly = to_tf32(v.y - __uint_as_float(hy));
    uint32_t lz = to_tf32(v.z - __uint_as_float(hz));
    uint32_t lw = to_tf32(v.w - __uint_as_float(hw));
    *reinterpret_cast<uint4*>(Bhi + f * ALD + kq * 4) = make_uint4(hx, hy, hz, hw);
    *reinterpret_cast<uint4*>(Blo + f * ALD + kq * 4) = make_uint4(lx, ly, lz, lw);
}

__global__ __launch_bounds__(BDIM)
void rrconv_mma_kernel(const float* __restrict__ x,
                       const float* __restrict__ Wg,
                       const float* __restrict__ bias,
                       float* __restrict__ out)
{
    extern __shared__ float sm[];
    float* bias_s = sm + OFF_BIAS;
    float* cells  = sm + OFF_CELL;
    float* tb     = sm + OFF_COEF;
    float* band   = sm + OFF_BAND;
    float* AhiB[2] = { sm + OFF_AHI0, sm + OFF_AHI1 };
    float* AloB[2] = { sm + OFF_ALO0, sm + OFF_ALO1 };
    float* BhiB[2] = { sm + OFF_BHI0, sm + OFF_BHI1 };
    float* BloB[2] = { sm + OFF_BLO0, sm + OFF_BLO1 };

    const int tid = threadIdx.x;
    const int wid = tid >> 5;
    const int lane = tid & 31;
    const int gid = lane >> 2;
    const int tig = lane & 3;
    const int ho0 = 2 * blockIdx.x;
    const int bb  = blockIdx.y;

    if (tid < 16)
        *reinterpret_cast<float4*>(bias_s + tid * 4) =
            *reinterpret_cast<const float4*>(bias + tid * 4);

    // ---- band: 8 rows x 64 cols x 32 ch, padded stride ----
    #pragma unroll
    for (int it = 0; it < 8; it++) {
        int t = tid + it * BDIM;
        int r = t >> 9, rem = t & 511, col = rem >> 3, c4 = rem & 7;
        *reinterpret_cast<float4*>(band + (r * 64 + col) * BLD + c4 * 4) =
            *reinterpret_cast<const float4*>(
                x + (((size_t)(bb * 64 + ho0 + r) * 64 + col) * 32 + c4 * 4));
    }
    __syncthreads();

    // ---- cell sums ----
    if (tid < 512) {
        const float4* s = reinterpret_cast<const float4*>(band + tid * BLD);
        float4 s0 = s[0], s1 = s[1], s2 = s[2], s3 = s[3];
        float4 s4 = s[4], s5 = s[5], s6 = s[6], s7 = s[7];
        cells[tid] =
            (((s0.x + s0.y) + (s0.z + s0.w)) + ((s1.x + s1.y) + (s1.z + s1.w)))
          + (((s2.x + s2.y) + (s2.z + s2.w)) + ((s3.x + s3.y) + (s3.z + s3.w)))
          + (((s4.x + s4.y) + (s4.z + s4.w)) + ((s5.x + s5.y) + (s5.z + s5.w)))
          + (((s6.x + s6.y) + (s6.z + s6.w)) + ((s7.x + s7.y) + (s7.z + s7.w)));
    }
    __syncthreads();

    // ---- centroid -> affine coeffs ----
    if (tid < 128) {
        int orow = tid >> 6, ocol = tid & 63;
        if (ocol < 58) {
            float tot = 0.f, sr = 0.f, sc = 0.f;
            #pragma unroll
            for (int i = 0; i < 7; i++)
                #pragma unroll
                for (int j = 0; j < 7; j++) {
                    float v = cells[(orow + i) * 64 + ocol + j];
                    tot += v; sr += v * (float)i; sc += v * (float)j;
                }
            float denom = tot + EPSF;
            float cr = sr / denom - 3.0f;
            float cc = sc / denom - 3.0f;
            float yv = cr, xv = cc + EPSF;
            float r2 = xv * xv + yv * yv;
            float cth = 1.f, sth = 0.f;
            if (r2 > 0.f) { float rn = sqrtf(r2); cth = xv / rn; sth = yv / rn; }
            const float scale = 1.0f + EPSF;
            tb[tid * 8 + 0] = cth / scale;
            tb[tid * 8 + 1] = -sth / scale;
            tb[tid * 8 + 2] = (3.f - 3.f * cth + 3.f * sth) / scale;
            tb[tid * 8 + 3] = sth / scale;
            tb[tid * 8 + 4] = (3.f - 3.f * sth - 3.f * cth) / scale;
        }
    }
    __syncthreads();

    const int mwarp = wid & 7;
    const int nwarp = wid >> 3;
    const int row0 = mwarp * 16 + gid;
    float acc[4][4];
    #pragma unroll
    for (int s = 0; s < 4; s++)
        #pragma unroll
        for (int q = 0; q < 4; q++) acc[s][q] = 0.f;

    // prologue: fill buffer 0 with chunk 0
    materialize(AhiB[0], AloB[0], band, tb, 0, tid);
    stageB(BhiB[0], BloB[0], Wg, 0, tid);
    __syncthreads();

    #pragma unroll 1
    for (int ch = 0; ch < NCHUNK; ch++) {
        const int b = ch & 1;
        // produce next chunk into the other buffer (overlaps MMA below)
        if (ch + 1 < NCHUNK) {
            materialize(AhiB[b ^ 1], AloB[b ^ 1], band, tb, ch + 1, tid);
            stageB(BhiB[b ^ 1], BloB[b ^ 1], Wg, ch + 1, tid);
        }
        // consume current buffer
        const uint32_t* Ah = reinterpret_cast<const uint32_t*>(AhiB[b]);
        const uint32_t* Al = reinterpret_cast<const uint32_t*>(AloB[b]);
        const uint32_t* Bh = reinterpret_cast<const uint32_t*>(BhiB[b]);
        const uint32_t* Bl = reinterpret_cast<const uint32_t*>(BloB[b]);
        #pragma unroll
        for (int kstep = 0; kstep < 4; kstep++) {
            int k2 = kstep * 8 + tig * 2;
            uint2 ah0 = *reinterpret_cast<const uint2*>(Ah + row0 * ALD + k2);
            uint2 ah1 = *reinterpret_cast<const uint2*>(Ah + (row0 + 8) * ALD + k2);
            uint2 al0 = *reinterpret_cast<const uint2*>(Al + row0 * ALD + k2);
            uint2 al1 = *reinterpret_cast<const uint2*>(Al + (row0 + 8) * ALD + k2);
            #pragma unroll
            for (int s = 0; s < 4; s++) {
                int n = nwarp * 32 + s * 8 + gid;
                uint2 bh = *reinterpret_cast<const uint2*>(Bh + n * ALD + k2);
                uint2 bl = *reinterpret_cast<const uint2*>(Bl + n * ALD + k2);
                mma8(acc[s], ah0.x, ah1.x, ah0.y, ah1.y, bh.x, bh.y);
                mma8(acc[s], al0.x, al1.x, al0.y, al1.y, bh.x, bh.y);
                mma8(acc[s], ah0.x, ah1.x, ah0.y, ah1.y, bl.x, bl.y);
            }
        }
        __syncthreads();
    }

    // ---- epilogue ----
    {
        int orow = row0 >> 6;
        int oc0 = row0 & 63;
        int oc1 = oc0 + 8;
        float* obase = out + ((size_t)(bb * 58 + ho0 + orow) * 58) * 64;
        #pragma unroll
        for (int s = 0; s < 4; s++) {
            int f = nwarp * 32 + s * 8 + tig * 2;
            float bx = bias_s[f], by = bias_s[f + 1];
            if (oc0 < 58)
                *reinterpret_cast<float2*>(obase + (size_t)oc0 * 64 + f) =
                    make_float2(acc[s][0] + bx, acc[s][1] + by);
            if (oc1 < 58)
                *reinterpret_cast<float2*>(obase + (size_t)oc1 * 64 + f) =
                    make_float2(acc[s][2] + bx, acc[s][3] + by);
        }
    }
}

extern "C" void kernel_launch(void* const* d_in, const int* in_sizes, int n_in,
                              void* d_out, int out_size)
{
    const float* x    = (const float*)d_in[0];
    const float* Wg   = (const float*)d_in[1];
    const float* bias = (const float*)d_in[2];
    float* out = (float*)d_out;

    const int smem_bytes = SMEM_FLOATS * 4;
    cudaFuncSetAttribute(rrconv_mma_kernel,
                         cudaFuncAttributeMaxDynamicSharedMemorySize, smem_bytes);
    dim3 grid(29, 8);   // output row-pairs, batch
    rrconv_mma_kernel<<<grid, BDIM, smem_bytes>>>(x, Wg, bias, out);
}

// round 17
// speedup vs baseline: 1.0035x; 1.0035x over previous
#include <cuda_runtime.h>
#include <cstdint>
#include <math.h>

#define BDIM 512
#define NCHUNK 25
#define ALD 36            // A/B smem row stride (floats)
#define BLD 36            // band cell stride (floats): 32 ch + 4 pad
#define EPSF 1e-7f

// smem float offsets
#define OFF_BIAS 0        // 64
#define OFF_CELL 64       // 512
#define OFF_COEF 576      // 128*8 = 1024
#define OFF_AHI0 1600     // 128*36 = 4608 each
#define OFF_ALO0 6208
#define OFF_AHI1 10816
#define OFF_ALO1 15424
#define OFF_BHI0 20032    // 64*36 = 2304 each
#define OFF_BLO0 22336
#define OFF_BHI1 24640
#define OFF_BLO1 26944
#define OFF_BAND 29248    // 512*36 = 18432
#define SMEM_FLOATS 47680 // 190720 bytes -> 1 CTA/SM

__device__ __forceinline__ uint32_t to_tf32(float f) {
    uint32_t r;
    asm("cvt.rna.tf32.f32 %0, %1;" : "=r"(r) : "f"(f));
    return r;
}

__device__ __forceinline__ void mma8(float* d,
        uint32_t a0, uint32_t a1, uint32_t a2, uint32_t a3,
        uint32_t b0, uint32_t b1) {
    asm volatile(
        "mma.sync.aligned.m16n8k8.row.col.f32.tf32.tf32.f32 "
        "{%0,%1,%2,%3}, {%4,%5,%6,%7}, {%8,%9}, {%0,%1,%2,%3};"
        : "+f"(d[0]), "+f"(d[1]), "+f"(d[2]), "+f"(d[3])
        : "r"(a0), "r"(a1), "r"(a2), "r"(a3), "r"(b0), "r"(b1));
}

// materialize chunk ch (one rotation position) into Ahi/Alo.
// task t = (px, c4), c4 fastest within warp -> conflict-light gather.
__device__ __forceinline__ void materialize(
    float* __restrict__ Ahi, float* __restrict__ Alo,
    const float* __restrict__ band, const float* __restrict__ tb,
    int ch, int tid)
{
    int py = ch / 5;
    float xg = (float)(ch - py * 5 + 1);
    float yg = (float)(py + 1);
    #pragma unroll
    for (int it = 0; it < 2; it++) {
        int t = tid + it * BDIM;
        int px = t >> 3, c4 = t & 7;
        int orow = px >> 6, ocol = px & 63;
        float4 w = make_float4(0.f, 0.f, 0.f, 0.f);
        unsigned cc00 = 0, cc01 = 0, cc10 = 0, cc11 = 0;
        if (ocol < 58) {
            float A0 = tb[px * 8 + 0], A1 = tb[px * 8 + 1], A2 = tb[px * 8 + 2];
            float A3 = tb[px * 8 + 3], A5 = tb[px * 8 + 4];
            float x_in = A0 * xg + A1 * yg + A2;
            float y_in = A3 * xg + A0 * yg + A5;
            float x0f = floorf(x_in), y0f = floorf(y_in);
            float wx1 = x_in - x0f, wx0 = 1.f - wx1;
            float wy1 = y_in - y0f, wy0 = 1.f - wy1;
            int ix0 = (int)x0f, iy0 = (int)y0f;
            int ix1 = ix0 + 1, iy1 = iy0 + 1;
            float vx0 = (ix0 >= 0 && ix0 < 7) ? 1.f : 0.f;
            float vx1 = (ix1 >= 0 && ix1 < 7) ? 1.f : 0.f;
            float vy0 = (iy0 >= 0 && iy0 < 7) ? 1.f : 0.f;
            float vy1 = (iy1 >= 0 && iy1 < 7) ? 1.f : 0.f;
            int cx0 = min(max(ix0, 0), 6), cx1 = min(max(ix1, 0), 6);
            int cy0 = min(max(iy0, 0), 6), cy1 = min(max(iy1, 0), 6);
            w = make_float4(wy0 * wx0 * vy0 * vx0, wy0 * wx1 * vy0 * vx1,
                            wy1 * wx0 * vy1 * vx0, wy1 * wx1 * vy1 * vx1);
            cc00 = (orow + cy0) * 64 + ocol + cx0;
            cc01 = (orow + cy0) * 64 + ocol + cx1;
            cc10 = (orow + cy1) * 64 + ocol + cx0;
            cc11 = (orow + cy1) * 64 + ocol + cx1;
        }
        int base = c4 * 4;
        const float4 v0 = *reinterpret_cast<const float4*>(band + cc00 * BLD + base);
        const float4 v1 = *reinterpret_cast<const float4*>(band + cc01 * BLD + base);
        const float4 v2 = *reinterpret_cast<const float4*>(band + cc10 * BLD + base);
        const float4 v3 = *reinterpret_cast<const float4*>(band + cc11 * BLD + base);
        float rx = fmaf(w.x, v0.x, fmaf(w.y, v1.x, fmaf(w.z, v2.x, w.w * v3.x)));
        float ry = fmaf(w.x, v0.y, fmaf(w.y, v1.y, fmaf(w.z, v2.y, w.w * v3.y)));
        float rz = fmaf(w.x, v0.z, fmaf(w.y, v1.z, fmaf(w.z, v2.z, w.w * v3.z)));
        float rw = fmaf(w.x, v0.w, fmaf(w.y, v1.w, fmaf(w.z, v2.w, w.w * v3.w)));
        uint32_t hx = to_tf32(rx), hy = to_tf32(ry), hz = to_tf32(rz), hw = to_tf32(rw);
        uint32_t lx = to_tf32(rx - __uint_as_float(hx));
        uint32_t ly = to_tf32(ry - __uint_as_float(hy));
        uint32_t lz = to_tf32(rz - __uint_as_float(hz));
        uint32_t lw = to_tf32(rw - __uint_as_float(hw));
        *reinterpret_cast<uint4*>(Ahi + px * ALD + base) = make_uint4(hx, hy, hz, hw);
        *reinterpret_cast<uint4*>(Alo + px * ALD + base) = make_uint4(lx, ly, lz, lw);
    }
}

__device__ __forceinline__ void stageB(
    float* __restrict__ Bhi, float* __restrict__ Blo,
    const float* __restrict__ Wg, int ch, int tid)
{
    int f = tid >> 3, kq = tid & 7;
    float4 v = *reinterpret_cast<const float4*>(Wg + f * 800 + ch * 32 + kq * 4);
    uint32_t hx = to_tf32(v.x), hy = to_tf32(v.y), hz = to_tf32(v.z), hw = to_tf32(v.w);
    uint32_t lx = to_tf32(v.x - __uint_as_float(hx));
    uint32_t ly = to_tf32(v.y - __uint_as_float(hy));
    uint32_t lz = to_tf32(v.z - __uint_as_float(hz));
    uint32_t lw = to_tf32(v.w - __uint_as_float(hw));
    *reinterpret_cast<uint4*>(Bhi + f * ALD + kq * 4) = make_uint4(hx, hy, hz, hw);
    *reinterpret_cast<uint4*>(Blo + f * ALD + kq * 4) = make_uint4(lx, ly, lz, lw);
}

__global__ __launch_bounds__(BDIM)
void rrconv_mma_kernel(const float* __restrict__ x,
                       const float* __restrict__ Wg,
                       const float* __restrict__ bias,
                       float* __restrict__ out)
{
    extern __shared__ float sm[];
    float* bias_s = sm + OFF_BIAS;
    float* cells  = sm + OFF_CELL;
    float* tb     = sm + OFF_COEF;
    float* band   = sm + OFF_BAND;
    float* AhiB[2] = { sm + OFF_AHI0, sm + OFF_AHI1 };
    float* AloB[2] = { sm + OFF_ALO0, sm + OFF_ALO1 };
    float* BhiB[2] = { sm + OFF_BHI0, sm + OFF_BHI1 };
    float* BloB[2] = { sm + OFF_BLO0, sm + OFF_BLO1 };

    const int tid = threadIdx.x;
    const int wid = tid >> 5;
    const int lane = tid & 31;
    const int gid = lane >> 2;
    const int tig = lane & 3;
    const int ho0 = 2 * blockIdx.x;
    const int bb  = blockIdx.y;

    if (tid < 16)
        *reinterpret_cast<float4*>(bias_s + tid * 4) =
            *reinterpret_cast<const float4*>(bias + tid * 4);

    // ---- band: 8 rows x 64 cols x 32 ch, padded stride ----
    #pragma unroll
    for (int it = 0; it < 8; it++) {
        int t = tid + it * BDIM;
        int r = t >> 9, rem = t & 511, col = rem >> 3, c4 = rem & 7;
        *reinterpret_cast<float4*>(band + (r * 64 + col) * BLD + c4 * 4) =
            *reinterpret_cast<const float4*>(
                x + (((size_t)(bb * 64 + ho0 + r) * 64 + col) * 32 + c4 * 4));
    }
    __syncthreads();

    // ---- cell sums ----
    if (tid < 512) {
        const float4* s = reinterpret_cast<const float4*>(band + tid * BLD);
        float4 s0 = s[0], s1 = s[1], s2 = s[2], s3 = s[3];
        float4 s4 = s[4], s5 = s[5], s6 = s[6], s7 = s[7];
        cells[tid] =
            (((s0.x + s0.y) + (s0.z + s0.w)) + ((s1.x + s1.y) + (s1.z + s1.w)))
          + (((s2.x + s2.y) + (s2.z + s2.w)) + ((s3.x + s3.y) + (s3.z + s3.w)))
          + (((s4.x + s4.y) + (s4.z + s4.w)) + ((s5.x + s5.y) + (s5.z + s5.w)))
          + (((s6.x + s6.y) + (s6.z + s6.w)) + ((s7.x + s7.y) + (s7.z + s7.w)));
    }
    __syncthreads();

    // ---- centroid -> affine coeffs ----
    if (tid < 128) {
        int orow = tid >> 6, ocol = tid & 63;
        if (ocol < 58) {
            float tot = 0.f, sr = 0.f, sc = 0.f;
            #pragma unroll
            for (int i = 0; i < 7; i++)
                #pragma unroll
                for (int j = 0; j < 7; j++) {
                    float v = cells[(orow + i) * 64 + ocol + j];
                    tot += v; sr += v * (float)i; sc += v * (float)j;
                }
            float denom = tot + EPSF;
            float cr = sr / denom - 3.0f;
            float cc = sc / denom - 3.0f;
            float yv = cr, xv = cc + EPSF;
            float r2 = xv * xv + yv * yv;
            float cth = 1.f, sth = 0.f;
            if (r2 > 0.f) { float rn = sqrtf(r2); cth = xv / rn; sth = yv / rn; }
            const float scale = 1.0f + EPSF;
            tb[tid * 8 + 0] = cth / scale;
            tb[tid * 8 + 1] = -sth / scale;
            tb[tid * 8 + 2] = (3.f - 3.f * cth + 3.f * sth) / scale;
            tb[tid * 8 + 3] = sth / scale;
            tb[tid * 8 + 4] = (3.f - 3.f * sth - 3.f * cth) / scale;
        }
    }
    __syncthreads();

    const int mwarp = wid & 7;
    const int nwarp = wid >> 3;
    const int row0 = mwarp * 16 + gid;
    float acc[4][4];
    #pragma unroll
    for (int s = 0; s < 4; s++)
        #pragma unroll
        for (int q = 0; q < 4; q++) acc[s][q] = 0.f;

    // prologue: fill buffer 0 with chunk 0
    materialize(AhiB[0], AloB[0], band, tb, 0, tid);
    stageB(BhiB[0], BloB[0], Wg, 0, tid);
    __syncthreads();

    #pragma unroll 1
    for (int ch = 0; ch < NCHUNK; ch++) {
        const int b = ch & 1;
        // produce next chunk into the other buffer (overlaps MMA below)
        if (ch + 1 < NCHUNK) {
            materialize(AhiB[b ^ 1], AloB[b ^ 1], band, tb, ch + 1, tid);
            stageB(BhiB[b ^ 1], BloB[b ^ 1], Wg, ch + 1, tid);
        }
        // consume current buffer
        const uint32_t* Ah = reinterpret_cast<const uint32_t*>(AhiB[b]);
        const uint32_t* Al = reinterpret_cast<const uint32_t*>(AloB[b]);
        const uint32_t* Bh = reinterpret_cast<const uint32_t*>(BhiB[b]);
        const uint32_t* Bl = reinterpret_cast<const uint32_t*>(BloB[b]);
        #pragma unroll
        for (int kstep = 0; kstep < 4; kstep++) {
            int k2 = kstep * 8 + tig * 2;
            uint2 ah0 = *reinterpret_cast<const uint2*>(Ah + row0 * ALD + k2);
            uint2 ah1 = *reinterpret_cast<const uint2*>(Ah + (row0 + 8) * ALD + k2);
            uint2 al0 = *reinterpret_cast<const uint2*>(Al + row0 * ALD + k2);
            uint2 al1 = *reinterpret_cast<const uint2*>(Al + (row0 + 8) * ALD + k2);
            #pragma unroll
            for (int s = 0; s < 4; s++) {
                int n = nwarp * 32 + s * 8 + gid;
                uint2 bh = *reinterpret_cast<const uint2*>(Bh + n * ALD + k2);
                uint2 bl = *reinterpret_cast<const uint2*>(Bl + n * ALD + k2);
                mma8(acc[s], ah0.x, ah1.x, ah0.y, ah1.y, bh.x, bh.y);
                mma8(acc[s], al0.x, al1.x, al0.y, al1.y, bh.x, bh.y);
                mma8(acc[s], ah0.x, ah1.x, ah0.y, ah1.y, bl.x, bl.y);
            }
        }
        __syncthreads();
    }

    // ---- epilogue ----
    {
        int orow = row0 >> 6;
        int oc0 = row0 & 63;
        int oc1 = oc0 + 8;
        float* obase = out + ((size_t)(bb * 58 + ho0 + orow) * 58) * 64;
        #pragma unroll
        for (int s = 0; s < 4; s++) {
            int f = nwarp * 32 + s * 8 + tig * 2;
            float bx = bias_s[f], by = bias_s[f + 1];
            if (oc0 < 58)
                *reinterpret_cast<float2*>(obase + (size_t)oc0 * 64 + f) =
                    make_float2(acc[s][0] + bx, acc[s][1] + by);
            if (oc1 < 58)
                *reinterpret_cast<float2*>(obase + (size_t)oc1 * 64 + f) =
                    make_float2(acc[s][2] + bx, acc[s][3] + by);
        }
    }
}

extern "C" void kernel_launch(void* const* d_in, const int* in_sizes, int n_in,
                              void* d_out, int out_size)
{
    const float* x    = (const float*)d_in[0];
    const float* Wg   = (const float*)d_in[1];
    const float* bias = (const float*)d_in[2];
    float* out = (float*)d_out;

    const int smem_bytes = SMEM_FLOATS * 4;
    cudaFuncSetAttribute(rrconv_mma_kernel,
                         cudaFuncAttributeMaxDynamicSharedMemorySize, smem_bytes);
    dim3 grid(29, 8);   // output row-pairs, batch
    rrconv_mma_kernel<<<grid, BDIM, smem_bytes>>>(x, Wg, bias, out);
}